// round 2
// baseline (speedup 1.0000x reference)
#include <cuda_runtime.h>
#include <stdint.h>

#define DIM 64
#define WARPS_PER_BLOCK 8
#define THREADS (WARPS_PER_BLOCK * 32)

__global__ void zero_kernel(float* __restrict__ h, int n) {
    int i = blockIdx.x * blockDim.x + threadIdx.x;
    if (i < n) h[i] = 0.0f;
}

__global__ __launch_bounds__(THREADS)
void distmult_edge_kernel(const float* __restrict__ node_emb,
                          const float* __restrict__ edge_emb,
                          const int* __restrict__ src,
                          const int* __restrict__ dst,
                          float* __restrict__ h_out,
                          float* __restrict__ dr_out,
                          int n_edges) {
    int warp_id = blockIdx.x * WARPS_PER_BLOCK + (threadIdx.x >> 5);
    int lane = threadIdx.x & 31;
    if (warp_id >= n_edges) return;

    int s = src[warp_id];
    int d = dst[warp_id];

    const float2* hp = reinterpret_cast<const float2*>(node_emb + (long long)s * DIM);
    const float2* tp = reinterpret_cast<const float2*>(node_emb + (long long)d * DIM);
    const float2* rp = reinterpret_cast<const float2*>(edge_emb + (long long)warp_id * DIM);

    float2 hh = hp[lane];
    float2 rr = rp[lane];
    float2 tt = tp[lane];

    // trans = head * rel; dr partial = trans * tail
    float t0 = hh.x * rr.x;
    float t1 = hh.y * rr.y;
    float p = fmaf(t1, tt.y, t0 * tt.x);

    // warp reduction over 32 lanes -> full 64-dim dot
    #pragma unroll
    for (int o = 16; o > 0; o >>= 1)
        p += __shfl_xor_sync(0xffffffffu, p, o);

    if (lane == 0) dr_out[warp_id] = p;

    float sig = 1.0f / (1.0f + __expf(-p));

    float* hd = h_out + (long long)d * DIM + 2 * lane;
    atomicAdd(hd,     sig * t0);
    atomicAdd(hd + 1, sig * t1);
}

extern "C" void kernel_launch(void* const* d_in, const int* in_sizes, int n_in,
                              void* d_out, int out_size) {
    const float* node_emb = (const float*)d_in[0];
    const float* edge_emb = (const float*)d_in[1];
    const int*   src      = (const int*)d_in[2];
    const int*   dst      = (const int*)d_in[3];

    int n_nodes = in_sizes[0] / DIM;
    int n_edges = in_sizes[1] / DIM;

    float* h_out  = (float*)d_out;                                // [N, D]
    float* dr_out = (float*)d_out + (long long)n_nodes * DIM;     // [E]

    int h_elems = n_nodes * DIM;
    zero_kernel<<<(h_elems + 255) / 256, 256>>>(h_out, h_elems);

    int blocks = (n_edges + WARPS_PER_BLOCK - 1) / WARPS_PER_BLOCK;
    distmult_edge_kernel<<<blocks, THREADS>>>(node_emb, edge_emb, src, dst,
                                              h_out, dr_out, n_edges);
}

// round 3
// speedup vs baseline: 1.5506x; 1.5506x over previous
#include <cuda_runtime.h>
#include <stdint.h>

#define DIM 64
#define WARPS_PER_BLOCK 8
#define THREADS (WARPS_PER_BLOCK * 32)
#define EDGES_PER_WARP 2

__global__ void zero_kernel4(float4* __restrict__ h, int n4) {
    int i = blockIdx.x * blockDim.x + threadIdx.x;
    if (i < n4) h[i] = make_float4(0.f, 0.f, 0.f, 0.f);
}

__global__ __launch_bounds__(THREADS)
void distmult_edge_kernel(const float* __restrict__ node_emb,
                          const float* __restrict__ edge_emb,
                          const int* __restrict__ src,
                          const int* __restrict__ dst,
                          float* __restrict__ h_out,
                          float* __restrict__ dr_out,
                          int n_edges) {
    int warp_id = blockIdx.x * WARPS_PER_BLOCK + (threadIdx.x >> 5);
    int lane    = threadIdx.x & 31;
    int half    = lane >> 4;        // which edge within the warp
    int l       = lane & 15;        // lane within the 16-lane group

    int e = warp_id * EDGES_PER_WARP + half;
    if (e >= n_edges) return;

    int s = src[e];
    int d = dst[e];

    const float4* hp = reinterpret_cast<const float4*>(node_emb + (long long)s * DIM);
    const float4* tp = reinterpret_cast<const float4*>(node_emb + (long long)d * DIM);
    const float4* rp = reinterpret_cast<const float4*>(edge_emb + (long long)e * DIM);

    float4 hh = hp[l];
    float4 rr = rp[l];
    float4 tt = tp[l];

    // trans = head * rel (kept for the message); partial dot = trans . tail
    float t0 = hh.x * rr.x;
    float t1 = hh.y * rr.y;
    float t2 = hh.z * rr.z;
    float t3 = hh.w * rr.w;

    float p = t0 * tt.x;
    p = fmaf(t1, tt.y, p);
    p = fmaf(t2, tt.z, p);
    p = fmaf(t3, tt.w, p);

    // 16-lane butterfly reduction (width 16 keeps the two edges independent)
    #pragma unroll
    for (int o = 8; o > 0; o >>= 1)
        p += __shfl_xor_sync(0xffffffffu, p, o, 16);

    if (l == 0) dr_out[e] = p;

    float sig = 1.0f / (1.0f + __expf(-p));

    float4 msg;
    msg.x = sig * t0;
    msg.y = sig * t1;
    msg.z = sig * t2;
    msg.w = sig * t3;

    float* hd = h_out + (long long)d * DIM + 4 * l;   // 16B-aligned
    asm volatile("red.global.add.v4.f32 [%0], {%1, %2, %3, %4};"
                 :: "l"(hd), "f"(msg.x), "f"(msg.y), "f"(msg.z), "f"(msg.w)
                 : "memory");
}

extern "C" void kernel_launch(void* const* d_in, const int* in_sizes, int n_in,
                              void* d_out, int out_size) {
    const float* node_emb = (const float*)d_in[0];
    const float* edge_emb = (const float*)d_in[1];
    const int*   src      = (const int*)d_in[2];
    const int*   dst      = (const int*)d_in[3];

    int n_nodes = in_sizes[0] / DIM;
    int n_edges = in_sizes[1] / DIM;

    float* h_out  = (float*)d_out;                                // [N, D]
    float* dr_out = (float*)d_out + (long long)n_nodes * DIM;     // [E]

    int h4 = n_nodes * DIM / 4;
    zero_kernel4<<<(h4 + 255) / 256, 256>>>((float4*)h_out, h4);

    int edges_per_block = WARPS_PER_BLOCK * EDGES_PER_WARP;
    int blocks = (n_edges + edges_per_block - 1) / edges_per_block;
    distmult_edge_kernel<<<blocks, THREADS>>>(node_emb, edge_emb, src, dst,
                                              h_out, dr_out, n_edges);
}

// round 7
// speedup vs baseline: 1.9245x; 1.2411x over previous
#include <cuda_runtime.h>
#include <stdint.h>

#define DIM 64
#define WARPS_PER_BLOCK 8
#define THREADS (WARPS_PER_BLOCK * 32)
#define EDGES_PER_WARP 4   // 2 lane-groups x 2 edges per thread

__global__ void zero_kernel4(float4* __restrict__ h, int n4) {
    int i = blockIdx.x * blockDim.x + threadIdx.x;
    if (i < n4) h[i] = make_float4(0.f, 0.f, 0.f, 0.f);
}

__global__ __launch_bounds__(THREADS)
void distmult_edge_kernel(const float* __restrict__ node_emb,
                          const float* __restrict__ edge_emb,
                          const int* __restrict__ src,
                          const int* __restrict__ dst,
                          float* __restrict__ h_out,
                          float* __restrict__ dr_out,
                          int n_edges) {
    int warp_id = blockIdx.x * WARPS_PER_BLOCK + (threadIdx.x >> 5);
    int lane    = threadIdx.x & 31;
    int half    = lane >> 4;        // lane-group within warp
    int l       = lane & 15;        // lane within 16-lane group

    int e0 = warp_id * EDGES_PER_WARP + half;
    int e1 = e0 + 2;
    bool v0 = e0 < n_edges;
    bool v1 = e1 < n_edges;
    // Clamp to safe indices; predicate only the stores. Loads of a duplicate
    // edge are harmless and keep the load batch branch-free.
    int ec0 = v0 ? e0 : n_edges - 1;
    int ec1 = v1 ? e1 : n_edges - 1;

    // ---- batched index loads (4 independent LDGs in flight) ----
    int s0 = src[ec0];
    int d0 = dst[ec0];
    int s1 = src[ec1];
    int d1 = dst[ec1];

    const float4* hp0 = reinterpret_cast<const float4*>(node_emb + (long long)s0 * DIM);
    const float4* tp0 = reinterpret_cast<const float4*>(node_emb + (long long)d0 * DIM);
    const float4* rp0 = reinterpret_cast<const float4*>(edge_emb + (long long)ec0 * DIM);
    const float4* hp1 = reinterpret_cast<const float4*>(node_emb + (long long)s1 * DIM);
    const float4* tp1 = reinterpret_cast<const float4*>(node_emb + (long long)d1 * DIM);
    const float4* rp1 = reinterpret_cast<const float4*>(edge_emb + (long long)ec1 * DIM);

    // ---- batched vector loads: 6 LDG.128 issued back-to-back ----
    float4 hh0 = hp0[l];
    float4 rr0 = rp0[l];
    float4 tt0 = tp0[l];
    float4 hh1 = hp1[l];
    float4 rr1 = rp1[l];
    float4 tt1 = tp1[l];

    // ---- edge 0 compute ----
    float a0 = hh0.x * rr0.x;
    float a1 = hh0.y * rr0.y;
    float a2 = hh0.z * rr0.z;
    float a3 = hh0.w * rr0.w;
    float p0 = a0 * tt0.x;
    p0 = fmaf(a1, tt0.y, p0);
    p0 = fmaf(a2, tt0.z, p0);
    p0 = fmaf(a3, tt0.w, p0);

    // ---- edge 1 compute ----
    float b0 = hh1.x * rr1.x;
    float b1 = hh1.y * rr1.y;
    float b2 = hh1.z * rr1.z;
    float b3 = hh1.w * rr1.w;
    float p1 = b0 * tt1.x;
    p1 = fmaf(b1, tt1.y, p1);
    p1 = fmaf(b2, tt1.z, p1);
    p1 = fmaf(b3, tt1.w, p1);

    // ---- two independent width-16 reductions ----
    #pragma unroll
    for (int o = 8; o > 0; o >>= 1) {
        p0 += __shfl_xor_sync(0xffffffffu, p0, o, 16);
        p1 += __shfl_xor_sync(0xffffffffu, p1, o, 16);
    }

    if (l == 0) {
        if (v0) dr_out[e0] = p0;
        if (v1) dr_out[e1] = p1;
    }

    float sig0 = 1.0f / (1.0f + __expf(-p0));
    float sig1 = 1.0f / (1.0f + __expf(-p1));

    if (v0) {
        float* hd = h_out + (long long)d0 * DIM + 4 * l;
        asm volatile("red.global.add.v4.f32 [%0], {%1, %2, %3, %4};"
                     :: "l"(hd), "f"(sig0 * a0), "f"(sig0 * a1),
                        "f"(sig0 * a2), "f"(sig0 * a3) : "memory");
    }
    if (v1) {
        float* hd = h_out + (long long)d1 * DIM + 4 * l;
        asm volatile("red.global.add.v4.f32 [%0], {%1, %2, %3, %4};"
                     :: "l"(hd), "f"(sig1 * b0), "f"(sig1 * b1),
                        "f"(sig1 * b2), "f"(sig1 * b3) : "memory");
    }
}

extern "C" void kernel_launch(void* const* d_in, const int* in_sizes, int n_in,
                              void* d_out, int out_size) {
    const float* node_emb = (const float*)d_in[0];
    const float* edge_emb = (const float*)d_in[1];
    const int*   src      = (const int*)d_in[2];
    const int*   dst      = (const int*)d_in[3];

    int n_nodes = in_sizes[0] / DIM;
    int n_edges = in_sizes[1] / DIM;

    float* h_out  = (float*)d_out;                                // [N, D]
    float* dr_out = (float*)d_out + (long long)n_nodes * DIM;     // [E]

    int h4 = n_nodes * DIM / 4;
    zero_kernel4<<<(h4 + 255) / 256, 256>>>((float4*)h_out, h4);

    int edges_per_block = WARPS_PER_BLOCK * EDGES_PER_WARP;
    int blocks = (n_edges + edges_per_block - 1) / edges_per_block;
    distmult_edge_kernel<<<blocks, THREADS>>>(node_emb, edge_emb, src, dst,
                                              h_out, dr_out, n_edges);
}